// round 12
// baseline (speedup 1.0000x reference)
#include <cuda_runtime.h>
#include <math.h>

#define B 16
#define HB 8               // batches per half
#define S 8192
#define C 256              // K_CH = D_MODEL
#define OUT 256
#define CHUNK 128
#define NCHUNK (S / CHUNK) // 64

// ---------------- scratch (no allocations allowed) ----------------
__device__ float g_qk[B * C];            // Wk @ q  per batch/channel
__device__ float g_bdot[B];              // q . bk
__device__ float g_m[B * NCHUNK];        // per-chunk score max
__device__ float g_l[B * NCHUNK];        // per-chunk sumexp (local max)
__device__ float g_cv[B * NCHUNK * C];   // per-chunk UNNORMALIZED weighted value sums
__device__ float g_po[B * 8 * OUT];      // partial projected outputs (8 c-slices)

// ---------------- kernel 1: prep (grid (HB,8), 256 thr) --------------
__global__ void prep_kernel(const float* __restrict__ query,
                            const float* __restrict__ Wq,
                            const float* __restrict__ bq,
                            const float* __restrict__ Wk,
                            const float* __restrict__ bk,
                            int b_off) {
    const int b = blockIdx.x + b_off;
    const int t = threadIdx.x;            // 0..255
    const int lane = t & 31, warp = t >> 5;
    __shared__ float q_sh[OUT];
    __shared__ float red[8];

    // redundant q projection (coalesced over t; Wq stays L2-hot)
    float acc = bq[t];
    const float* qrow = query + b * C;
    #pragma unroll 8
    for (int d = 0; d < C; d++)
        acc += qrow[d] * Wq[d * OUT + t];
    q_sh[t] = acc;

    if (blockIdx.y == 0) {
        float v = acc * bk[t];
        #pragma unroll
        for (int off = 16; off; off >>= 1)
            v += __shfl_xor_sync(0xffffffffu, v, off);
        if (lane == 0) red[warp] = v;
    }
    __syncthreads();
    if (blockIdx.y == 0 && t == 0) {
        float s = red[0];
        #pragma unroll
        for (int i = 1; i < 8; i++) s += red[i];
        g_bdot[b] = s;
    }

    // qk: this block's 32 channels; warp handles 4 channels sequentially
    const float4* q4 = (const float4*)q_sh;
    #pragma unroll
    for (int i = 0; i < 4; i++) {
        const int c = blockIdx.y * 32 + warp * 4 + i;
        const float4* w4 = (const float4*)(Wk + (size_t)c * OUT);
        float a = 0.f;
        #pragma unroll
        for (int j = 0; j < 2; j++) {
            float4 w = w4[lane + 32 * j];
            float4 q = q4[lane + 32 * j];
            a += w.x * q.x + w.y * q.y + w.z * q.z + w.w * q.w;
        }
        #pragma unroll
        for (int off = 16; off; off >>= 1)
            a += __shfl_xor_sync(0xffffffffu, a, off);
        if (lane == 0) g_qk[b * C + c] = a;
    }
}

// ---------------- kernel 2: fused key+value scan (grid (NCHUNK,HB)) --
__global__ void partial_kernel(const float* __restrict__ key,
                               const float* __restrict__ value,
                               int b_off) {
    const int b = blockIdx.y + b_off;
    const int s0 = blockIdx.x * CHUNK;
    const int t = threadIdx.x, lane = t & 31, warp = t >> 5;

    __shared__ float qk_sh[C];
    __shared__ float p_sh[CHUNK];
    __shared__ float redm[4], redl[4];
    __shared__ float4 red4[4][OUT / 4];

    qk_sh[t] = g_qk[b * C + t];
    __syncthreads();

    const float bd = g_bdot[b];
    const float scale = 0.0625f;  // 1/sqrt(256)
    const float4* qk4 = (const float4*)qk_sh;

    // ---- phase 1: each warp 16 rows, 4 in flight
    #pragma unroll
    for (int g = 0; g < 4; g++) {
        const int r0 = warp * 16 + g * 4;
        const float* base = key + ((size_t)b * S + s0 + r0) * C;
        const float4* k0 = (const float4*)(base);
        const float4* k1 = (const float4*)(base + C);
        const float4* k2 = (const float4*)(base + 2 * C);
        const float4* k3 = (const float4*)(base + 3 * C);
        float a0 = 0.f, a1 = 0.f, a2 = 0.f, a3 = 0.f;
        #pragma unroll
        for (int j = 0; j < 2; j++) {
            const int idx = lane + 32 * j;
            float4 q = qk4[idx];
            float4 x0 = __ldcs(&k0[idx]);
            float4 x1 = __ldcs(&k1[idx]);
            float4 x2 = __ldcs(&k2[idx]);
            float4 x3 = __ldcs(&k3[idx]);
            a0 += x0.x * q.x + x0.y * q.y + x0.z * q.z + x0.w * q.w;
            a1 += x1.x * q.x + x1.y * q.y + x1.z * q.z + x1.w * q.w;
            a2 += x2.x * q.x + x2.y * q.y + x2.z * q.z + x2.w * q.w;
            a3 += x3.x * q.x + x3.y * q.y + x3.z * q.z + x3.w * q.w;
        }
        #pragma unroll
        for (int off = 16; off; off >>= 1) {
            a0 += __shfl_xor_sync(0xffffffffu, a0, off);
            a1 += __shfl_xor_sync(0xffffffffu, a1, off);
            a2 += __shfl_xor_sync(0xffffffffu, a2, off);
            a3 += __shfl_xor_sync(0xffffffffu, a3, off);
        }
        if (lane == 0) {
            p_sh[r0]     = (a0 + bd) * scale;
            p_sh[r0 + 1] = (a1 + bd) * scale;
            p_sh[r0 + 2] = (a2 + bd) * scale;
            p_sh[r0 + 3] = (a3 + bd) * scale;
        }
    }
    __syncthreads();

    // ---- local softmax partials (threads 0..127)
    float sc = 0.f;
    if (t < CHUNK) {
        sc = p_sh[t];
        float v = sc;
        #pragma unroll
        for (int off = 16; off; off >>= 1)
            v = fmaxf(v, __shfl_xor_sync(0xffffffffu, v, off));
        if (lane == 0) redm[warp] = v;
    }
    __syncthreads();
    const float m = fmaxf(fmaxf(redm[0], redm[1]), fmaxf(redm[2], redm[3]));
    if (t < CHUNK) {
        const float p = __expf(sc - m);
        p_sh[t] = p;                    // own index; visible after next sync
        float sv = p;
        #pragma unroll
        for (int off = 16; off; off >>= 1)
            sv += __shfl_xor_sync(0xffffffffu, sv, off);
        if (lane == 0) redl[warp] = sv;
    }
    __syncthreads();   // weights + redl visible

    // ---- phase 2: float4 column walk, unroll 8
    const int cq = t & 63;
    const int rg = t >> 6;
    const float4* vb = (const float4*)(value + ((size_t)b * S + s0) * C) + cq;
    float4 acc = make_float4(0.f, 0.f, 0.f, 0.f);
    #pragma unroll 8
    for (int s = rg; s < CHUNK; s += 4) {
        const float4 x = __ldcs(&vb[(size_t)s * (C / 4)]);
        const float ws = p_sh[s];
        acc.x += ws * x.x; acc.y += ws * x.y;
        acc.z += ws * x.z; acc.w += ws * x.w;
    }
    red4[rg][cq] = acc;
    __syncthreads();

    const int pidx = b * NCHUNK + blockIdx.x;
    if (t < 64) {
        float4 a0 = red4[0][t], a1 = red4[1][t], a2 = red4[2][t], a3 = red4[3][t];
        float4 r;
        r.x = (a0.x + a1.x) + (a2.x + a3.x);
        r.y = (a0.y + a1.y) + (a2.y + a3.y);
        r.z = (a0.z + a1.z) + (a2.z + a3.z);
        r.w = (a0.w + a1.w) + (a2.w + a3.w);
        ((float4*)(g_cv + (size_t)pidx * C))[t] = r;
    }
    if (t == 0) {
        g_m[pidx] = m;
        g_l[pidx] = redl[0] + redl[1] + redl[2] + redl[3];
    }
}

// ---------------- kernel 3: softmax fixup + projection (grid (HB,8)) -
__global__ void project_part_kernel(const float* __restrict__ Wv, int b_off) {
    const int b = blockIdx.x + b_off;
    const int y = blockIdx.y;
    const int t = threadIdx.x, lane = t & 31, warp = t >> 5;

    __shared__ float redm[2], redl[2];
    __shared__ float shA[8][32];
    __shared__ float cx_sh[32];

    // --- gm / gl (threads 0..63 hold the 64 chunk partials)
    float pm = -INFINITY, pl = 0.f;
    if (t < NCHUNK) {
        pm = g_m[b * NCHUNK + t];
        pl = g_l[b * NCHUNK + t];
    }
    float v = pm;
    #pragma unroll
    for (int off = 16; off; off >>= 1)
        v = fmaxf(v, __shfl_xor_sync(0xffffffffu, v, off));
    if (lane == 0 && warp < 2) redm[warp] = v;
    __syncthreads();
    const float gm = fmaxf(redm[0], redm[1]);
    float w = pl * __expf(pm - gm);
    #pragma unroll
    for (int off = 16; off; off >>= 1)
        w += __shfl_xor_sync(0xffffffffu, w, off);
    if (lane == 0 && warp < 2) redl[warp] = w;
    __syncthreads();
    const float gli = 1.f / (redl[0] + redl[1]);

    // --- phase A: warp w sums chunks i = 8w..8w+7 with weight exp(m_i-gm)
    const size_t cvbase = ((size_t)(b * NCHUNK + warp * 8)) * C + y * 32 + lane;
    float a = 0.f;
    #pragma unroll
    for (int i = 0; i < 8; i++) {
        const float wi = __expf(g_m[b * NCHUNK + warp * 8 + i] - gm);
        a += wi * g_cv[cvbase + (size_t)i * C];
    }
    shA[warp][lane] = a;
    __syncthreads();

    if (t < 32) {
        float s = shA[0][t];
        #pragma unroll
        for (int ww = 1; ww < 8; ww++) s += shA[ww][t];
        cx_sh[t] = s * gli;
    }
    __syncthreads();

    // --- phase B: 32-iteration coalesced Wv walk
    float o = 0.f;
    const float* wv = Wv + (size_t)(y * 32) * OUT + t;
    #pragma unroll 8
    for (int j = 0; j < 32; j++)
        o += cx_sh[j] * wv[(size_t)j * OUT];
    g_po[(size_t)(b * 8 + y) * OUT + t] = o;
}

// ---------------- kernel 4: assemble ctx + broadcast (grid (S/64,HB)) -
__global__ void bcast_kernel(const float* __restrict__ bv,
                             float* __restrict__ out, int b_off) {
    const int b = blockIdx.y + b_off;
    const int t = threadIdx.x;
    __shared__ float4 ctx4[OUT / 4];  // 64
    if (t < OUT / 4) {
        float4 acc = ((const float4*)bv)[t];
        const float4* po4 = (const float4*)(g_po + (size_t)b * 8 * OUT);
        #pragma unroll
        for (int y = 0; y < 8; y++) {
            const float4 p = po4[y * (OUT / 4) + t];
            acc.x += p.x; acc.y += p.y; acc.z += p.z; acc.w += p.w;
        }
        ctx4[t] = acc;
    }
    __syncthreads();

    const int row = t >> 6;   // 0..3
    const int col = t & 63;   // 0..63
    const float4 val = ctx4[col];
    float4* o4 = (float4*)out;
    const size_t base = ((size_t)b * S + (size_t)blockIdx.x * 64) * (C / 4);
    #pragma unroll
    for (int i = 0; i < 16; i++)
        __stcs(&o4[base + (size_t)(i * 4 + row) * (OUT / 4) + col], val);
}

// ---------------- stream/event context (created on first, uncaptured call)
struct PipeCtx {
    cudaStream_t s2;
    cudaEvent_t e_fork, e_pA, e_join;
    PipeCtx() {
        cudaStreamCreateWithFlags(&s2, cudaStreamNonBlocking);
        cudaEventCreateWithFlags(&e_fork, cudaEventDisableTiming);
        cudaEventCreateWithFlags(&e_pA, cudaEventDisableTiming);
        cudaEventCreateWithFlags(&e_join, cudaEventDisableTiming);
    }
};

// ---------------- launch: 2-half fork/join pipeline -------------------
extern "C" void kernel_launch(void* const* d_in, const int* in_sizes, int n_in,
                              void* d_out, int out_size) {
    const float* query = (const float*)d_in[0];
    const float* key   = (const float*)d_in[1];
    const float* value = (const float*)d_in[2];
    const float* Wq    = (const float*)d_in[3];
    const float* bq    = (const float*)d_in[4];
    const float* Wk    = (const float*)d_in[5];
    const float* bk    = (const float*)d_in[6];
    const float* Wv    = (const float*)d_in[7];
    const float* bv    = (const float*)d_in[8];
    float* out = (float*)d_out;

    static PipeCtx ctx;   // constructed during the uncaptured correctness call
    cudaStream_t s0 = 0, s2 = ctx.s2;

    // fork: s2 joins the capture via event dependency
    cudaEventRecord(ctx.e_fork, s0);
    cudaStreamWaitEvent(s2, ctx.e_fork, 0);

    // half A (batches 0..7) on s0, half B (batches 8..15) on s2
    prep_kernel<<<dim3(HB, 8), 256, 0, s0>>>(query, Wq, bq, Wk, bk, 0);
    prep_kernel<<<dim3(HB, 8), 256, 0, s2>>>(query, Wq, bq, Wk, bk, HB);

    partial_kernel<<<dim3(NCHUNK, HB), 256, 0, s0>>>(key, value, 0);
    cudaEventRecord(ctx.e_pA, s0);
    cudaStreamWaitEvent(s2, ctx.e_pA, 0);          // serialize the two read scans
    partial_kernel<<<dim3(NCHUNK, HB), 256, 0, s2>>>(key, value, HB);

    // half A's write burst overlaps half B's read scan
    project_part_kernel<<<dim3(HB, 8), 256, 0, s0>>>(Wv, 0);
    bcast_kernel<<<dim3(S / 64, HB), 256, 0, s0>>>(bv, out, 0);

    project_part_kernel<<<dim3(HB, 8), 256, 0, s2>>>(Wv, HB);
    bcast_kernel<<<dim3(S / 64, HB), 256, 0, s2>>>(bv, out, HB);

    // join: s0 waits for s2's tail
    cudaEventRecord(ctx.e_join, s2);
    cudaStreamWaitEvent(s0, ctx.e_join, 0);
}

// round 13
// speedup vs baseline: 1.0145x; 1.0145x over previous
#include <cuda_runtime.h>
#include <math.h>

#define B 16
#define S 8192
#define C 256      // K_CH = D_MODEL
#define OUT 256
#define CHUNK 128
#define NCHUNK (S / CHUNK)   // 64

// ---------------- scratch (no allocations allowed) ----------------
__device__ float g_qk[B * C];            // Wk @ q  per batch/channel
__device__ float g_bdot[B];              // q . bk
__device__ float g_m[B * NCHUNK];        // per-chunk score max
__device__ float g_l[B * NCHUNK];        // per-chunk sumexp (local max)
__device__ float g_cv[B * NCHUNK * C];   // per-chunk UNNORMALIZED weighted value sums
__device__ float g_po[B * 8 * OUT];      // partial projected outputs (8 c-slices)

// ---------------- kernel 1: prep (grid (B,8), 256 thr) ---------------
__global__ void prep_kernel(const float* __restrict__ query,
                            const float* __restrict__ Wq,
                            const float* __restrict__ bq,
                            const float* __restrict__ Wk,
                            const float* __restrict__ bk) {
    const int b = blockIdx.x;
    const int t = threadIdx.x;            // 0..255
    const int lane = t & 31, warp = t >> 5;
    __shared__ float q_sh[OUT];
    __shared__ float red[8];

    // redundant q projection (coalesced over t; Wq stays L2-hot)
    float acc = bq[t];
    const float* qrow = query + b * C;
    #pragma unroll 8
    for (int d = 0; d < C; d++)
        acc += qrow[d] * Wq[d * OUT + t];
    q_sh[t] = acc;

    if (blockIdx.y == 0) {
        float v = acc * bk[t];
        #pragma unroll
        for (int off = 16; off; off >>= 1)
            v += __shfl_xor_sync(0xffffffffu, v, off);
        if (lane == 0) red[warp] = v;
    }
    __syncthreads();
    if (blockIdx.y == 0 && t == 0) {
        float s = red[0];
        #pragma unroll
        for (int i = 1; i < 8; i++) s += red[i];
        g_bdot[b] = s;
    }

    // qk: this block's 32 channels; warp handles 4 channels sequentially
    const float4* q4 = (const float4*)q_sh;
    #pragma unroll
    for (int i = 0; i < 4; i++) {
        const int c = blockIdx.y * 32 + warp * 4 + i;
        const float4* w4 = (const float4*)(Wk + (size_t)c * OUT);
        float a = 0.f;
        #pragma unroll
        for (int j = 0; j < 2; j++) {
            float4 w = w4[lane + 32 * j];
            float4 q = q4[lane + 32 * j];
            a += w.x * q.x + w.y * q.y + w.z * q.z + w.w * q.w;
        }
        #pragma unroll
        for (int off = 16; off; off >>= 1)
            a += __shfl_xor_sync(0xffffffffu, a, off);
        if (lane == 0) g_qk[b * C + c] = a;
    }
}

// ---------------- kernel 2: fused key+value scan (grid (NCHUNK,B)) ---
// __launch_bounds__(256, 6): cap regs at 42 -> 6 resident blocks/SM
// phase 1: scores (reads key, 4 rows in flight / warp)
// phase 2: local softmax + unnormalized weighted value sums (reads value)
__global__ void __launch_bounds__(256, 6)
partial_kernel(const float* __restrict__ key,
               const float* __restrict__ value) {
    const int b = blockIdx.y;
    const int s0 = blockIdx.x * CHUNK;
    const int t = threadIdx.x, lane = t & 31, warp = t >> 5;

    __shared__ float qk_sh[C];
    __shared__ float p_sh[CHUNK];
    __shared__ float redm[4], redl[4];
    __shared__ float4 red4[4][OUT / 4];

    qk_sh[t] = g_qk[b * C + t];
    __syncthreads();

    const float bd = g_bdot[b];
    const float scale = 0.0625f;  // 1/sqrt(256)
    const float4* qk4 = (const float4*)qk_sh;

    // ---- phase 1: each warp 16 rows, 4 in flight
    #pragma unroll
    for (int g = 0; g < 4; g++) {
        const int r0 = warp * 16 + g * 4;
        const float* base = key + ((size_t)b * S + s0 + r0) * C;
        const float4* k0 = (const float4*)(base);
        const float4* k1 = (const float4*)(base + C);
        const float4* k2 = (const float4*)(base + 2 * C);
        const float4* k3 = (const float4*)(base + 3 * C);
        float a0 = 0.f, a1 = 0.f, a2 = 0.f, a3 = 0.f;
        #pragma unroll
        for (int j = 0; j < 2; j++) {
            const int idx = lane + 32 * j;
            float4 q = qk4[idx];
            float4 x0 = __ldcs(&k0[idx]);
            float4 x1 = __ldcs(&k1[idx]);
            float4 x2 = __ldcs(&k2[idx]);
            float4 x3 = __ldcs(&k3[idx]);
            a0 += x0.x * q.x + x0.y * q.y + x0.z * q.z + x0.w * q.w;
            a1 += x1.x * q.x + x1.y * q.y + x1.z * q.z + x1.w * q.w;
            a2 += x2.x * q.x + x2.y * q.y + x2.z * q.z + x2.w * q.w;
            a3 += x3.x * q.x + x3.y * q.y + x3.z * q.z + x3.w * q.w;
        }
        #pragma unroll
        for (int off = 16; off; off >>= 1) {
            a0 += __shfl_xor_sync(0xffffffffu, a0, off);
            a1 += __shfl_xor_sync(0xffffffffu, a1, off);
            a2 += __shfl_xor_sync(0xffffffffu, a2, off);
            a3 += __shfl_xor_sync(0xffffffffu, a3, off);
        }
        if (lane == 0) {
            p_sh[r0]     = (a0 + bd) * scale;
            p_sh[r0 + 1] = (a1 + bd) * scale;
            p_sh[r0 + 2] = (a2 + bd) * scale;
            p_sh[r0 + 3] = (a3 + bd) * scale;
        }
    }
    __syncthreads();

    // ---- local softmax partials (threads 0..127)
    float sc = 0.f;
    if (t < CHUNK) {
        sc = p_sh[t];
        float v = sc;
        #pragma unroll
        for (int off = 16; off; off >>= 1)
            v = fmaxf(v, __shfl_xor_sync(0xffffffffu, v, off));
        if (lane == 0) redm[warp] = v;
    }
    __syncthreads();
    const float m = fmaxf(fmaxf(redm[0], redm[1]), fmaxf(redm[2], redm[3]));
    if (t < CHUNK) {
        const float p = __expf(sc - m);
        p_sh[t] = p;                    // own index; visible after next sync
        float sv = p;
        #pragma unroll
        for (int off = 16; off; off >>= 1)
            sv += __shfl_xor_sync(0xffffffffu, sv, off);
        if (lane == 0) redl[warp] = sv;
    }
    __syncthreads();   // weights + redl visible

    // ---- phase 2: float4 column walk, unroll 8
    const int cq = t & 63;
    const int rg = t >> 6;
    const float4* vb = (const float4*)(value + ((size_t)b * S + s0) * C) + cq;
    float4 acc = make_float4(0.f, 0.f, 0.f, 0.f);
    #pragma unroll 8
    for (int s = rg; s < CHUNK; s += 4) {
        const float4 x = __ldcs(&vb[(size_t)s * (C / 4)]);
        const float ws = p_sh[s];
        acc.x += ws * x.x; acc.y += ws * x.y;
        acc.z += ws * x.z; acc.w += ws * x.w;
    }
    red4[rg][cq] = acc;
    __syncthreads();

    const int pidx = b * NCHUNK + blockIdx.x;
    if (t < 64) {
        float4 a0 = red4[0][t], a1 = red4[1][t], a2 = red4[2][t], a3 = red4[3][t];
        float4 r;
        r.x = (a0.x + a1.x) + (a2.x + a3.x);
        r.y = (a0.y + a1.y) + (a2.y + a3.y);
        r.z = (a0.z + a1.z) + (a2.z + a3.z);
        r.w = (a0.w + a1.w) + (a2.w + a3.w);
        ((float4*)(g_cv + (size_t)pidx * C))[t] = r;
    }
    if (t == 0) {
        g_m[pidx] = m;
        g_l[pidx] = redl[0] + redl[1] + redl[2] + redl[3];
    }
}

// ---------------- kernel 3: softmax fixup + projection (grid (B,8)) --
__global__ void project_part_kernel(const float* __restrict__ Wv) {
    const int b = blockIdx.x;
    const int y = blockIdx.y;
    const int t = threadIdx.x, lane = t & 31, warp = t >> 5;

    __shared__ float redm[2], redl[2];
    __shared__ float shA[8][32];
    __shared__ float cx_sh[32];

    // --- gm / gl (threads 0..63 hold the 64 chunk partials)
    float pm = -INFINITY, pl = 0.f;
    if (t < NCHUNK) {
        pm = g_m[b * NCHUNK + t];
        pl = g_l[b * NCHUNK + t];
    }
    float v = pm;
    #pragma unroll
    for (int off = 16; off; off >>= 1)
        v = fmaxf(v, __shfl_xor_sync(0xffffffffu, v, off));
    if (lane == 0 && warp < 2) redm[warp] = v;
    __syncthreads();
    const float gm = fmaxf(redm[0], redm[1]);
    float w = pl * __expf(pm - gm);
    #pragma unroll
    for (int off = 16; off; off >>= 1)
        w += __shfl_xor_sync(0xffffffffu, w, off);
    if (lane == 0 && warp < 2) redl[warp] = w;
    __syncthreads();
    const float gli = 1.f / (redl[0] + redl[1]);

    // --- phase A: warp w sums chunks i = 8w..8w+7 with weight exp(m_i-gm)
    const size_t cvbase = ((size_t)(b * NCHUNK + warp * 8)) * C + y * 32 + lane;
    float a = 0.f;
    #pragma unroll
    for (int i = 0; i < 8; i++) {
        const float wi = __expf(g_m[b * NCHUNK + warp * 8 + i] - gm);
        a += wi * g_cv[cvbase + (size_t)i * C];
    }
    shA[warp][lane] = a;
    __syncthreads();

    if (t < 32) {
        float s = shA[0][t];
        #pragma unroll
        for (int ww = 1; ww < 8; ww++) s += shA[ww][t];
        cx_sh[t] = s * gli;
    }
    __syncthreads();

    // --- phase B: 32-iteration coalesced Wv walk
    float o = 0.f;
    const float* wv = Wv + (size_t)(y * 32) * OUT + t;
    #pragma unroll 8
    for (int j = 0; j < 32; j++)
        o += cx_sh[j] * wv[(size_t)j * OUT];
    g_po[(size_t)(b * 8 + y) * OUT + t] = o;
}

// ---------------- kernel 4: assemble ctx + broadcast over S ----------
__global__ void __launch_bounds__(256, 8)
bcast_kernel(const float* __restrict__ bv,
             float* __restrict__ out) {
    const int b = blockIdx.y;
    const int t = threadIdx.x;
    __shared__ float4 ctx4[OUT / 4];  // 64
    if (t < OUT / 4) {
        float4 acc = ((const float4*)bv)[t];
        const float4* po4 = (const float4*)(g_po + (size_t)b * 8 * OUT);
        #pragma unroll
        for (int y = 0; y < 8; y++) {
            const float4 p = po4[y * (OUT / 4) + t];
            acc.x += p.x; acc.y += p.y; acc.z += p.z; acc.w += p.w;
        }
        ctx4[t] = acc;
    }
    __syncthreads();

    const int row = t >> 6;   // 0..3
    const int col = t & 63;   // 0..63
    const float4 val = ctx4[col];
    float4* o4 = (float4*)out;
    const size_t base = ((size_t)b * S + (size_t)blockIdx.x * 64) * (C / 4);
    #pragma unroll
    for (int i = 0; i < 16; i++)
        __stcs(&o4[base + (size_t)(i * 4 + row) * (OUT / 4) + col], val);
}

// ---------------- launch ------------------
extern "C" void kernel_launch(void* const* d_in, const int* in_sizes, int n_in,
                              void* d_out, int out_size) {
    const float* query = (const float*)d_in[0];
    const float* key   = (const float*)d_in[1];
    const float* value = (const float*)d_in[2];
    const float* Wq    = (const float*)d_in[3];
    const float* bq    = (const float*)d_in[4];
    const float* Wk    = (const float*)d_in[5];
    const float* bk    = (const float*)d_in[6];
    const float* Wv    = (const float*)d_in[7];
    const float* bv    = (const float*)d_in[8];
    float* out = (float*)d_out;

    prep_kernel<<<dim3(B, 8), 256>>>(query, Wq, bq, Wk, bk);
    partial_kernel<<<dim3(NCHUNK, B), 256>>>(key, value);
    project_part_kernel<<<dim3(B, 8), 256>>>(Wv);
    bcast_kernel<<<dim3(S / 64, B), 256>>>(bv, out);
}

// round 14
// speedup vs baseline: 1.0441x; 1.0292x over previous
#include <cuda_runtime.h>
#include <math.h>

#define B 16
#define S 8192
#define C 256      // K_CH = D_MODEL
#define OUT 256
#define CHUNK 128
#define NCHUNK (S / CHUNK)   // 64

// ---------------- scratch (no allocations allowed) ----------------
__device__ float g_qk[B * C];            // Wk @ q  per batch/channel
__device__ float g_bdot[B];              // q . bk
__device__ float g_m[B * NCHUNK];        // per-chunk score max
__device__ float g_l[B * NCHUNK];        // per-chunk sumexp (local max)
__device__ float g_cv[B * NCHUNK * C];   // per-chunk UNNORMALIZED weighted value sums
__device__ float g_po[B * 8 * OUT];      // partial projected outputs (8 c-slices)
__device__ int   g_cnt[B];               // arrival counters (self-resetting)
__device__ int   g_done[B];              // projection-done counters (self-resetting)

// ---------------- kernel 1: prep (grid (B,8), 256 thr) ---------------
__global__ void prep_kernel(const float* __restrict__ query,
                            const float* __restrict__ Wq,
                            const float* __restrict__ bq,
                            const float* __restrict__ Wk,
                            const float* __restrict__ bk) {
    const int b = blockIdx.x;
    const int t = threadIdx.x;            // 0..255
    const int lane = t & 31, warp = t >> 5;
    __shared__ float q_sh[OUT];
    __shared__ float red[8];

    // redundant q projection (coalesced over t; Wq stays L2-hot)
    float acc = bq[t];
    const float* qrow = query + b * C;
    #pragma unroll 8
    for (int d = 0; d < C; d++)
        acc += qrow[d] * Wq[d * OUT + t];
    q_sh[t] = acc;

    if (blockIdx.y == 0) {
        float v = acc * bk[t];
        #pragma unroll
        for (int off = 16; off; off >>= 1)
            v += __shfl_xor_sync(0xffffffffu, v, off);
        if (lane == 0) red[warp] = v;
    }
    __syncthreads();
    if (blockIdx.y == 0 && t == 0) {
        float s = red[0];
        #pragma unroll
        for (int i = 1; i < 8; i++) s += red[i];
        g_bdot[b] = s;
    }

    // qk: this block's 32 channels; warp handles 4 channels sequentially
    const float4* q4 = (const float4*)q_sh;
    #pragma unroll
    for (int i = 0; i < 4; i++) {
        const int c = blockIdx.y * 32 + warp * 4 + i;
        const float4* w4 = (const float4*)(Wk + (size_t)c * OUT);
        float a = 0.f;
        #pragma unroll
        for (int j = 0; j < 2; j++) {
            float4 w = w4[lane + 32 * j];
            float4 q = q4[lane + 32 * j];
            a += w.x * q.x + w.y * q.y + w.z * q.z + w.w * q.w;
        }
        #pragma unroll
        for (int off = 16; off; off >>= 1)
            a += __shfl_xor_sync(0xffffffffu, a, off);
        if (lane == 0) g_qk[b * C + c] = a;
    }
}

// ---------------- kernel 2: fused scan + tail projection -------------
// grid (NCHUNK, B), 256 thr. launch_bounds(256,5) = natural 51-reg cap.
// After a block's partials are written, the last 8 arrivals per batch
// each take one channel-slice and run the softmax fixup + Wv projection.
__global__ void __launch_bounds__(256, 5)
partial_kernel(const float* __restrict__ key,
               const float* __restrict__ value,
               const float* __restrict__ Wv) {
    const int b = blockIdx.y;
    const int s0 = blockIdx.x * CHUNK;
    const int t = threadIdx.x, lane = t & 31, warp = t >> 5;

    __shared__ float qk_sh[C];
    __shared__ float p_sh[CHUNK];
    __shared__ float redm[4], redl[4];
    __shared__ float4 red4[4][OUT / 4];
    __shared__ float shA[8][32];
    __shared__ float cx_sh[32];
    __shared__ int   ord_sh;

    qk_sh[t] = g_qk[b * C + t];
    __syncthreads();

    const float bd = g_bdot[b];
    const float scale = 0.0625f;  // 1/sqrt(256)
    const float4* qk4 = (const float4*)qk_sh;

    // ---- phase 1: each warp 16 rows, 4 in flight
    #pragma unroll
    for (int g = 0; g < 4; g++) {
        const int r0 = warp * 16 + g * 4;
        const float* base = key + ((size_t)b * S + s0 + r0) * C;
        const float4* k0 = (const float4*)(base);
        const float4* k1 = (const float4*)(base + C);
        const float4* k2 = (const float4*)(base + 2 * C);
        const float4* k3 = (const float4*)(base + 3 * C);
        float a0 = 0.f, a1 = 0.f, a2 = 0.f, a3 = 0.f;
        #pragma unroll
        for (int j = 0; j < 2; j++) {
            const int idx = lane + 32 * j;
            float4 q = qk4[idx];
            float4 x0 = __ldcs(&k0[idx]);
            float4 x1 = __ldcs(&k1[idx]);
            float4 x2 = __ldcs(&k2[idx]);
            float4 x3 = __ldcs(&k3[idx]);
            a0 += x0.x * q.x + x0.y * q.y + x0.z * q.z + x0.w * q.w;
            a1 += x1.x * q.x + x1.y * q.y + x1.z * q.z + x1.w * q.w;
            a2 += x2.x * q.x + x2.y * q.y + x2.z * q.z + x2.w * q.w;
            a3 += x3.x * q.x + x3.y * q.y + x3.z * q.z + x3.w * q.w;
        }
        #pragma unroll
        for (int off = 16; off; off >>= 1) {
            a0 += __shfl_xor_sync(0xffffffffu, a0, off);
            a1 += __shfl_xor_sync(0xffffffffu, a1, off);
            a2 += __shfl_xor_sync(0xffffffffu, a2, off);
            a3 += __shfl_xor_sync(0xffffffffu, a3, off);
        }
        if (lane == 0) {
            p_sh[r0]     = (a0 + bd) * scale;
            p_sh[r0 + 1] = (a1 + bd) * scale;
            p_sh[r0 + 2] = (a2 + bd) * scale;
            p_sh[r0 + 3] = (a3 + bd) * scale;
        }
    }
    __syncthreads();

    // ---- local softmax partials (threads 0..127)
    float sc = 0.f;
    if (t < CHUNK) {
        sc = p_sh[t];
        float v = sc;
        #pragma unroll
        for (int off = 16; off; off >>= 1)
            v = fmaxf(v, __shfl_xor_sync(0xffffffffu, v, off));
        if (lane == 0) redm[warp] = v;
    }
    __syncthreads();
    const float m = fmaxf(fmaxf(redm[0], redm[1]), fmaxf(redm[2], redm[3]));
    if (t < CHUNK) {
        const float p = __expf(sc - m);
        p_sh[t] = p;                    // own index; visible after next sync
        float sv = p;
        #pragma unroll
        for (int off = 16; off; off >>= 1)
            sv += __shfl_xor_sync(0xffffffffu, sv, off);
        if (lane == 0) redl[warp] = sv;
    }
    __syncthreads();   // weights + redl visible

    // ---- phase 2: float4 column walk, unroll 8
    const int cq = t & 63;
    const int rg = t >> 6;
    const float4* vb = (const float4*)(value + ((size_t)b * S + s0) * C) + cq;
    float4 acc = make_float4(0.f, 0.f, 0.f, 0.f);
    #pragma unroll 8
    for (int s = rg; s < CHUNK; s += 4) {
        const float4 x = __ldcs(&vb[(size_t)s * (C / 4)]);
        const float ws = p_sh[s];
        acc.x += ws * x.x; acc.y += ws * x.y;
        acc.z += ws * x.z; acc.w += ws * x.w;
    }
    red4[rg][cq] = acc;
    __syncthreads();

    const int pidx = b * NCHUNK + blockIdx.x;
    if (t < 64) {
        float4 a0 = red4[0][t], a1 = red4[1][t], a2 = red4[2][t], a3 = red4[3][t];
        float4 r;
        r.x = (a0.x + a1.x) + (a2.x + a3.x);
        r.y = (a0.y + a1.y) + (a2.y + a3.y);
        r.z = (a0.z + a1.z) + (a2.z + a3.z);
        r.w = (a0.w + a1.w) + (a2.w + a3.w);
        ((float4*)(g_cv + (size_t)pidx * C))[t] = r;
    }
    if (t == 0) {
        g_m[pidx] = m;
        g_l[pidx] = redl[0] + redl[1] + redl[2] + redl[3];
    }

    // ---- arrival count (threadfence-reduction pattern)
    __threadfence();
    __syncthreads();
    if (t == 0) ord_sh = atomicAdd(&g_cnt[b], 1);
    __syncthreads();
    const int ord = ord_sh;
    if (ord < NCHUNK - 8) return;

    // === tail projection: this block owns channel slice y ===
    const int y = ord - (NCHUNK - 8);
    if (t == 0) {
        while (atomicAdd(&g_cnt[b], 0) < NCHUNK) __nanosleep(64);
    }
    __syncthreads();
    __threadfence();   // acquire: all 64 chunks' partials now visible

    // gm / gl (threads 0..63 hold the 64 chunk partials)
    float pm = -INFINITY, pl = 0.f;
    if (t < NCHUNK) {
        pm = g_m[b * NCHUNK + t];
        pl = g_l[b * NCHUNK + t];
    }
    float v2 = pm;
    #pragma unroll
    for (int off = 16; off; off >>= 1)
        v2 = fmaxf(v2, __shfl_xor_sync(0xffffffffu, v2, off));
    if (lane == 0 && warp < 2) redm[warp] = v2;
    __syncthreads();
    const float gm = fmaxf(redm[0], redm[1]);
    float w2 = pl * __expf(pm - gm);
    #pragma unroll
    for (int off = 16; off; off >>= 1)
        w2 += __shfl_xor_sync(0xffffffffu, w2, off);
    if (lane == 0 && warp < 2) redl[warp] = w2;
    __syncthreads();
    const float gli = 1.f / (redl[0] + redl[1]);

    // phase A: warp w sums chunks 8w..8w+7 with weight exp(m_i-gm)
    const size_t cvbase = ((size_t)(b * NCHUNK + warp * 8)) * C + y * 32 + lane;
    float a = 0.f;
    #pragma unroll
    for (int i = 0; i < 8; i++) {
        const float wi = __expf(g_m[b * NCHUNK + warp * 8 + i] - gm);
        a += wi * g_cv[cvbase + (size_t)i * C];
    }
    shA[warp][lane] = a;
    __syncthreads();

    if (t < 32) {
        float s = shA[0][t];
        #pragma unroll
        for (int ww = 1; ww < 8; ww++) s += shA[ww][t];
        cx_sh[t] = s * gli;
    }
    __syncthreads();

    // phase B: 32-iteration coalesced Wv walk
    float o = 0.f;
    const float* wv = Wv + (size_t)(y * 32) * OUT + t;
    #pragma unroll 8
    for (int j = 0; j < 32; j++)
        o += cx_sh[j] * wv[(size_t)j * OUT];
    g_po[(size_t)(b * 8 + y) * OUT + t] = o;

    // reset counters for the next graph replay (last projector per batch)
    __threadfence();
    if (t == 0) {
        const int d = atomicAdd(&g_done[b], 1);
        if (d == 7) { g_cnt[b] = 0; g_done[b] = 0; __threadfence(); }
    }
}

// ---------------- kernel 3: assemble ctx + broadcast over S ----------
__global__ void __launch_bounds__(256, 8)
bcast_kernel(const float* __restrict__ bv,
             float* __restrict__ out) {
    const int b = blockIdx.y;
    const int t = threadIdx.x;
    __shared__ float4 ctx4[OUT / 4];  // 64
    if (t < OUT / 4) {
        float4 acc = ((const float4*)bv)[t];
        const float4* po4 = (const float4*)(g_po + (size_t)b * 8 * OUT);
        #pragma unroll
        for (int y = 0; y < 8; y++) {
            const float4 p = po4[y * (OUT / 4) + t];
            acc.x += p.x; acc.y += p.y; acc.z += p.z; acc.w += p.w;
        }
        ctx4[t] = acc;
    }
    __syncthreads();

    const int row = t >> 6;   // 0..3
    const int col = t & 63;   // 0..63
    const float4 val = ctx4[col];
    float4* o4 = (float4*)out;
    const size_t base = ((size_t)b * S + (size_t)blockIdx.x * 64) * (C / 4);
    #pragma unroll
    for (int i = 0; i < 16; i++)
        __stcs(&o4[base + (size_t)(i * 4 + row) * (OUT / 4) + col], val);
}

// ---------------- launch ------------------
extern "C" void kernel_launch(void* const* d_in, const int* in_sizes, int n_in,
                              void* d_out, int out_size) {
    const float* query = (const float*)d_in[0];
    const float* key   = (const float*)d_in[1];
    const float* value = (const float*)d_in[2];
    const float* Wq    = (const float*)d_in[3];
    const float* bq    = (const float*)d_in[4];
    const float* Wk    = (const float*)d_in[5];
    const float* bk    = (const float*)d_in[6];
    const float* Wv    = (const float*)d_in[7];
    const float* bv    = (const float*)d_in[8];
    float* out = (float*)d_out;

    prep_kernel<<<dim3(B, 8), 256>>>(query, Wq, bq, Wk, bk);
    partial_kernel<<<dim3(NCHUNK, B), 256>>>(key, value, Wv);
    bcast_kernel<<<dim3(S / 64, B), 256>>>(bv, out);
}

// round 15
// speedup vs baseline: 1.0466x; 1.0024x over previous
#include <cuda_runtime.h>
#include <math.h>

#define B 16
#define S 8192
#define C 256      // K_CH = D_MODEL
#define OUT 256
#define CHUNK 128
#define NCHUNK (S / CHUNK)   // 64

// ---------------- scratch (no allocations allowed) ----------------
__device__ float g_qk[B * C];            // Wk @ q  per batch/channel
__device__ float g_bdot[B];              // q . bk
__device__ float g_m[B * NCHUNK];        // per-chunk score max
__device__ float g_l[B * NCHUNK];        // per-chunk sumexp (local max)
__device__ float g_cv[B * NCHUNK * C];   // per-chunk UNNORMALIZED weighted value sums
__device__ float g_po[B * 8 * OUT];      // partial projected outputs (8 c-slices)
__device__ int   g_cnt[B];               // arrival counters (self-resetting)
__device__ int   g_done[B];              // projection-done counters (self-resetting)

// ---------------- kernel 1: prep (grid (B,8), 256 thr) ---------------
// q projection with warp-split d-loop: warp w covers d in [32w,32w+32),
// thread (w,l) accumulates 8 outputs -> 8 KB shared partial, then reduce.
__global__ void prep_kernel(const float* __restrict__ query,
                            const float* __restrict__ Wq,
                            const float* __restrict__ bq,
                            const float* __restrict__ Wk,
                            const float* __restrict__ bk) {
    const int b = blockIdx.x;
    const int t = threadIdx.x;            // 0..255
    const int lane = t & 31, warp = t >> 5;
    __shared__ float x_sh[C];
    __shared__ float qpart[8][OUT];       // 8 KB
    __shared__ float q_sh[OUT];
    __shared__ float red[8];

    x_sh[t] = query[b * C + t];
    __syncthreads();

    // step A: partial dot over this warp's 32 d-values, 8 outputs/thread
    float a0 = 0.f, a1 = 0.f, a2 = 0.f, a3 = 0.f;
    float a4 = 0.f, a5 = 0.f, a6 = 0.f, a7 = 0.f;
    #pragma unroll 4
    for (int dd = 0; dd < 32; dd++) {
        const int d = warp * 32 + dd;
        const float x = x_sh[d];
        const float* wrow = Wq + (size_t)d * OUT + lane;
        a0 += x * wrow[0];
        a1 += x * wrow[32];
        a2 += x * wrow[64];
        a3 += x * wrow[96];
        a4 += x * wrow[128];
        a5 += x * wrow[160];
        a6 += x * wrow[192];
        a7 += x * wrow[224];
    }
    qpart[warp][lane]       = a0;
    qpart[warp][lane + 32]  = a1;
    qpart[warp][lane + 64]  = a2;
    qpart[warp][lane + 96]  = a3;
    qpart[warp][lane + 128] = a4;
    qpart[warp][lane + 160] = a5;
    qpart[warp][lane + 192] = a6;
    qpart[warp][lane + 224] = a7;
    __syncthreads();

    // step B: reduce partials + bias
    float qv = bq[t];
    #pragma unroll
    for (int w = 0; w < 8; w++) qv += qpart[w][t];
    q_sh[t] = qv;

    // bdot (block y==0 only)
    if (blockIdx.y == 0) {
        float v = qv * bk[t];
        #pragma unroll
        for (int off = 16; off; off >>= 1)
            v += __shfl_xor_sync(0xffffffffu, v, off);
        if (lane == 0) red[warp] = v;
    }
    __syncthreads();
    if (blockIdx.y == 0 && t == 0) {
        float s = red[0];
        #pragma unroll
        for (int i = 1; i < 8; i++) s += red[i];
        g_bdot[b] = s;
    }

    // step C: qk for this block's 32 channels; warp = 4 channels
    const float4* q4 = (const float4*)q_sh;
    #pragma unroll
    for (int i = 0; i < 4; i++) {
        const int c = blockIdx.y * 32 + warp * 4 + i;
        const float4* w4 = (const float4*)(Wk + (size_t)c * OUT);
        float a = 0.f;
        #pragma unroll
        for (int j = 0; j < 2; j++) {
            float4 w = w4[lane + 32 * j];
            float4 q = q4[lane + 32 * j];
            a += w.x * q.x + w.y * q.y + w.z * q.z + w.w * q.w;
        }
        #pragma unroll
        for (int off = 16; off; off >>= 1)
            a += __shfl_xor_sync(0xffffffffu, a, off);
        if (lane == 0) g_qk[b * C + c] = a;
    }
}

// ---------------- kernel 2: fused scan + tail projection -------------
// grid (NCHUNK, B), 256 thr. Last 8 arrivals per batch project a slice.
__global__ void __launch_bounds__(256, 5)
partial_kernel(const float* __restrict__ key,
               const float* __restrict__ value,
               const float* __restrict__ Wv) {
    const int b = blockIdx.y;
    const int s0 = blockIdx.x * CHUNK;
    const int t = threadIdx.x, lane = t & 31, warp = t >> 5;

    __shared__ float qk_sh[C];
    __shared__ float p_sh[CHUNK];
    __shared__ float redm[4], redl[4];
    __shared__ float4 red4[4][OUT / 4];
    __shared__ float shA[8][32];
    __shared__ float cx_sh[32];
    __shared__ int   ord_sh;

    qk_sh[t] = g_qk[b * C + t];
    __syncthreads();

    const float bd = g_bdot[b];
    const float scale = 0.0625f;  // 1/sqrt(256)
    const float4* qk4 = (const float4*)qk_sh;

    // ---- phase 1: each warp 16 rows, 4 in flight
    #pragma unroll
    for (int g = 0; g < 4; g++) {
        const int r0 = warp * 16 + g * 4;
        const float* base = key + ((size_t)b * S + s0 + r0) * C;
        const float4* k0 = (const float4*)(base);
        const float4* k1 = (const float4*)(base + C);
        const float4* k2 = (const float4*)(base + 2 * C);
        const float4* k3 = (const float4*)(base + 3 * C);
        float a0 = 0.f, a1 = 0.f, a2 = 0.f, a3 = 0.f;
        #pragma unroll
        for (int j = 0; j < 2; j++) {
            const int idx = lane + 32 * j;
            float4 q = qk4[idx];
            float4 x0 = __ldcs(&k0[idx]);
            float4 x1 = __ldcs(&k1[idx]);
            float4 x2 = __ldcs(&k2[idx]);
            float4 x3 = __ldcs(&k3[idx]);
            a0 += x0.x * q.x + x0.y * q.y + x0.z * q.z + x0.w * q.w;
            a1 += x1.x * q.x + x1.y * q.y + x1.z * q.z + x1.w * q.w;
            a2 += x2.x * q.x + x2.y * q.y + x2.z * q.z + x2.w * q.w;
            a3 += x3.x * q.x + x3.y * q.y + x3.z * q.z + x3.w * q.w;
        }
        #pragma unroll
        for (int off = 16; off; off >>= 1) {
            a0 += __shfl_xor_sync(0xffffffffu, a0, off);
            a1 += __shfl_xor_sync(0xffffffffu, a1, off);
            a2 += __shfl_xor_sync(0xffffffffu, a2, off);
            a3 += __shfl_xor_sync(0xffffffffu, a3, off);
        }
        if (lane == 0) {
            p_sh[r0]     = (a0 + bd) * scale;
            p_sh[r0 + 1] = (a1 + bd) * scale;
            p_sh[r0 + 2] = (a2 + bd) * scale;
            p_sh[r0 + 3] = (a3 + bd) * scale;
        }
    }
    __syncthreads();

    // ---- local softmax partials (threads 0..127)
    float sc = 0.f;
    if (t < CHUNK) {
        sc = p_sh[t];
        float v = sc;
        #pragma unroll
        for (int off = 16; off; off >>= 1)
            v = fmaxf(v, __shfl_xor_sync(0xffffffffu, v, off));
        if (lane == 0) redm[warp] = v;
    }
    __syncthreads();
    const float m = fmaxf(fmaxf(redm[0], redm[1]), fmaxf(redm[2], redm[3]));
    if (t < CHUNK) {
        const float p = __expf(sc - m);
        p_sh[t] = p;                    // own index; visible after next sync
        float sv = p;
        #pragma unroll
        for (int off = 16; off; off >>= 1)
            sv += __shfl_xor_sync(0xffffffffu, sv, off);
        if (lane == 0) redl[warp] = sv;
    }
    __syncthreads();   // weights + redl visible

    // ---- phase 2: float4 column walk, unroll 8
    const int cq = t & 63;
    const int rg = t >> 6;
    const float4* vb = (const float4*)(value + ((size_t)b * S + s0) * C) + cq;
    float4 acc = make_float4(0.f, 0.f, 0.f, 0.f);
    #pragma unroll 8
    for (int s = rg; s < CHUNK; s += 4) {
        const float4 x = __ldcs(&vb[(size_t)s * (C / 4)]);
        const float ws = p_sh[s];
        acc.x += ws * x.x; acc.y += ws * x.y;
        acc.z += ws * x.z; acc.w += ws * x.w;
    }
    red4[rg][cq] = acc;
    __syncthreads();

    const int pidx = b * NCHUNK + blockIdx.x;
    if (t < 64) {
        float4 a0 = red4[0][t], a1 = red4[1][t], a2 = red4[2][t], a3 = red4[3][t];
        float4 r;
        r.x = (a0.x + a1.x) + (a2.x + a3.x);
        r.y = (a0.y + a1.y) + (a2.y + a3.y);
        r.z = (a0.z + a1.z) + (a2.z + a3.z);
        r.w = (a0.w + a1.w) + (a2.w + a3.w);
        ((float4*)(g_cv + (size_t)pidx * C))[t] = r;
    }
    if (t == 0) {
        g_m[pidx] = m;
        g_l[pidx] = redl[0] + redl[1] + redl[2] + redl[3];
    }

    // ---- arrival count (threadfence-reduction pattern)
    __threadfence();
    __syncthreads();
    if (t == 0) ord_sh = atomicAdd(&g_cnt[b], 1);
    __syncthreads();
    const int ord = ord_sh;
    if (ord < NCHUNK - 8) return;

    // === tail projection: this block owns channel slice y ===
    const int y = ord - (NCHUNK - 8);
    if (t == 0) {
        while (atomicAdd(&g_cnt[b], 0) < NCHUNK) __nanosleep(64);
    }
    __syncthreads();
    __threadfence();   // acquire: all 64 chunks' partials now visible

    // gm / gl (threads 0..63 hold the 64 chunk partials)
    float pm = -INFINITY, pl = 0.f;
    if (t < NCHUNK) {
        pm = g_m[b * NCHUNK + t];
        pl = g_l[b * NCHUNK + t];
    }
    float v2 = pm;
    #pragma unroll
    for (int off = 16; off; off >>= 1)
        v2 = fmaxf(v2, __shfl_xor_sync(0xffffffffu, v2, off));
    if (lane == 0 && warp < 2) redm[warp] = v2;
    __syncthreads();
    const float gm = fmaxf(redm[0], redm[1]);
    float w2 = pl * __expf(pm - gm);
    #pragma unroll
    for (int off = 16; off; off >>= 1)
        w2 += __shfl_xor_sync(0xffffffffu, w2, off);
    if (lane == 0 && warp < 2) redl[warp] = w2;
    __syncthreads();
    const float gli = 1.f / (redl[0] + redl[1]);

    // phase A: warp w sums chunks 8w..8w+7 with weight exp(m_i-gm)
    const size_t cvbase = ((size_t)(b * NCHUNK + warp * 8)) * C + y * 32 + lane;
    float a = 0.f;
    #pragma unroll
    for (int i = 0; i < 8; i++) {
        const float wi = __expf(g_m[b * NCHUNK + warp * 8 + i] - gm);
        a += wi * g_cv[cvbase + (size_t)i * C];
    }
    shA[warp][lane] = a;
    __syncthreads();

    if (t < 32) {
        float s = shA[0][t];
        #pragma unroll
        for (int ww = 1; ww < 8; ww++) s += shA[ww][t];
        cx_sh[t] = s * gli;
    }
    __syncthreads();

    // phase B: 32-iteration coalesced Wv walk
    float o = 0.f;
    const float* wv = Wv + (size_t)(y * 32) * OUT + t;
    #pragma unroll 8
    for (int j = 0; j < 32; j++)
        o += cx_sh[j] * wv[(size_t)j * OUT];
    g_po[(size_t)(b * 8 + y) * OUT + t] = o;

    // reset counters for the next graph replay (last projector per batch)
    __threadfence();
    if (t == 0) {
        const int d = atomicAdd(&g_done[b], 1);
        if (d == 7) { g_cnt[b] = 0; g_done[b] = 0; __threadfence(); }
    }
}

// ---------------- kernel 3: assemble ctx + broadcast over S ----------
__global__ void __launch_bounds__(256, 8)
bcast_kernel(const float* __restrict__ bv,
             float* __restrict__ out) {
    const int b = blockIdx.y;
    const int t = threadIdx.x;
    __shared__ float4 ctx4[OUT / 4];  // 64
    if (t < OUT / 4) {
        float4 acc = ((const float4*)bv)[t];
        const float4* po4 = (const float4*)(g_po + (size_t)b * 8 * OUT);
        #pragma unroll
        for (int y = 0; y < 8; y++) {
            const float4 p = po4[y * (OUT / 4) + t];
            acc.x += p.x; acc.y += p.y; acc.z += p.z; acc.w += p.w;
        }
        ctx4[t] = acc;
    }
    __syncthreads();

    const int row = t >> 6;   // 0..3
    const int col = t & 63;   // 0..63
    const float4 val = ctx4[col];
    float4* o4 = (float4*)out;
    const size_t base = ((size_t)b * S + (size_t)blockIdx.x * 64) * (C / 4);
    #pragma unroll
    for (int i = 0; i < 16; i++)
        __stcs(&o4[base + (size_t)(i * 4 + row) * (OUT / 4) + col], val);
}

// ---------------- launch ------------------
extern "C" void kernel_launch(void* const* d_in, const int* in_sizes, int n_in,
                              void* d_out, int out_size) {
    const float* query = (const float*)d_in[0];
    const float* key   = (const float*)d_in[1];
    const float* value = (const float*)d_in[2];
    const float* Wq    = (const float*)d_in[3];
    const float* bq    = (const float*)d_in[4];
    const float* Wk    = (const float*)d_in[5];
    const float* bk    = (const float*)d_in[6];
    const float* Wv    = (const float*)d_in[7];
    const float* bv    = (const float*)d_in[8];
    float* out = (float*)d_out;

    prep_kernel<<<dim3(B, 8), 256>>>(query, Wq, bq, Wk, bk);
    partial_kernel<<<dim3(NCHUNK, B), 256>>>(key, value, Wv);
    bcast_kernel<<<dim3(S / 64, B), 256>>>(bv, out);
}

// round 16
// speedup vs baseline: 1.0926x; 1.0440x over previous
#include <cuda_runtime.h>
#include <math.h>

#define B 16
#define S 8192
#define C 256      // K_CH = D_MODEL
#define OUT 256
#define CHUNK 128
#define NCHUNK (S / CHUNK)   // 64

// ---------------- scratch (no allocations allowed) ----------------
__device__ float g_qk[B * C];            // Wk @ q  per batch/channel
__device__ float g_bdot[B];              // q . bk
__device__ float g_qpart[B * 8 * OUT];   // q partials (8 d-slices per batch)
__device__ float g_m[B * NCHUNK];        // per-chunk score max
__device__ float g_l[B * NCHUNK];        // per-chunk sumexp (local max)
__device__ float g_cv[B * NCHUNK * C];   // per-chunk UNNORMALIZED weighted value sums
__device__ float g_po[B * 8 * OUT];      // partial projected outputs (8 c-slices)
__device__ int   g_cnt[B];               // scan arrival counters (self-resetting)
__device__ int   g_done[B];              // projection-done counters (self-resetting)
__device__ int   g_pcnt[B];              // prep arrival counters (self-resetting)
__device__ int   g_pdone[B];             // prep done counters (self-resetting)

// ---------------- kernel 1: cooperative prep (grid (B,8), 256 thr) ---
// block y: q-partial over d in [32y,32y+32) (no redundant Wq reads),
// counter barrier, reduce 8 partials (L2-hot), bdot (y==0), qk slice.
__global__ void prep_kernel(const float* __restrict__ query,
                            const float* __restrict__ Wq,
                            const float* __restrict__ bq,
                            const float* __restrict__ Wk,
                            const float* __restrict__ bk) {
    const int b = blockIdx.x;
    const int y = blockIdx.y;
    const int t = threadIdx.x;            // 0..255
    const int lane = t & 31, warp = t >> 5;
    __shared__ float x_sh[32];
    __shared__ float q_sh[OUT];
    __shared__ float red[8];

    if (t < 32) x_sh[t] = query[b * C + y * 32 + t];
    __syncthreads();

    // ---- q-partial: output t, 32 fully-independent coalesced loads
    float a0 = 0.f, a1 = 0.f, a2 = 0.f, a3 = 0.f;
    #pragma unroll
    for (int dd = 0; dd < 32; dd += 4) {
        const size_t base = (size_t)(y * 32 + dd) * OUT + t;
        a0 += x_sh[dd]     * Wq[base];
        a1 += x_sh[dd + 1] * Wq[base + OUT];
        a2 += x_sh[dd + 2] * Wq[base + 2 * OUT];
        a3 += x_sh[dd + 3] * Wq[base + 3 * OUT];
    }
    g_qpart[(size_t)(b * 8 + y) * OUT + t] = (a0 + a1) + (a2 + a3);

    // ---- release + arrive
    __threadfence();
    __syncthreads();
    if (t == 0) {
        atomicAdd(&g_pcnt[b], 1);
        while (atomicAdd(&g_pcnt[b], 0) < 8) __nanosleep(32);
    }
    __syncthreads();
    __threadfence();   // acquire: all 8 partials visible

    // ---- reduce partials + bias (8 independent L2-hot loads)
    float qv = bq[t];
    #pragma unroll
    for (int i = 0; i < 8; i++)
        qv += g_qpart[(size_t)(b * 8 + i) * OUT + t];
    q_sh[t] = qv;

    // bdot (block y==0 only)
    if (y == 0) {
        float v = qv * bk[t];
        #pragma unroll
        for (int off = 16; off; off >>= 1)
            v += __shfl_xor_sync(0xffffffffu, v, off);
        if (lane == 0) red[warp] = v;
    }
    __syncthreads();
    if (y == 0 && t == 0) {
        float s = red[0];
        #pragma unroll
        for (int i = 1; i < 8; i++) s += red[i];
        g_bdot[b] = s;
    }

    // ---- qk for this block's 32 channels; warp = 4 channels
    const float4* q4 = (const float4*)q_sh;
    #pragma unroll
    for (int i = 0; i < 4; i++) {
        const int c = y * 32 + warp * 4 + i;
        const float4* w4 = (const float4*)(Wk + (size_t)c * OUT);
        float a = 0.f;
        #pragma unroll
        for (int j = 0; j < 2; j++) {
            float4 w = w4[lane + 32 * j];
            float4 q = q4[lane + 32 * j];
            a += w.x * q.x + w.y * q.y + w.z * q.z + w.w * q.w;
        }
        #pragma unroll
        for (int off = 16; off; off >>= 1)
            a += __shfl_xor_sync(0xffffffffu, a, off);
        if (lane == 0) g_qk[b * C + c] = a;
    }

    // ---- reset prep counters for next graph replay
    __threadfence();
    if (t == 0) {
        const int d = atomicAdd(&g_pdone[b], 1);
        if (d == 7) { g_pcnt[b] = 0; g_pdone[b] = 0; __threadfence(); }
    }
}

// ---------------- kernel 2: fused scan + tail projection -------------
// grid (NCHUNK, B), 256 thr. Last 8 arrivals per batch project a slice.
__global__ void __launch_bounds__(256, 5)
partial_kernel(const float* __restrict__ key,
               const float* __restrict__ value,
               const float* __restrict__ Wv) {
    const int b = blockIdx.y;
    const int s0 = blockIdx.x * CHUNK;
    const int t = threadIdx.x, lane = t & 31, warp = t >> 5;

    __shared__ float qk_sh[C];
    __shared__ float p_sh[CHUNK];
    __shared__ float redm[4], redl[4];
    __shared__ float4 red4[4][OUT / 4];
    __shared__ float shA[8][32];
    __shared__ float cx_sh[32];
    __shared__ int   ord_sh;

    qk_sh[t] = g_qk[b * C + t];
    __syncthreads();

    const float bd = g_bdot[b];
    const float scale = 0.0625f;  // 1/sqrt(256)
    const float4* qk4 = (const float4*)qk_sh;

    // ---- phase 1: each warp 16 rows, 4 in flight
    #pragma unroll
    for (int g = 0; g < 4; g++) {
        const int r0 = warp * 16 + g * 4;
        const float* base = key + ((size_t)b * S + s0 + r0) * C;
        const float4* k0 = (const float4*)(base);
        const float4* k1 = (const float4*)(base + C);
        const float4* k2 = (const float4*)(base + 2 * C);
        const float4* k3 = (const float4*)(base + 3 * C);
        float a0 = 0.f, a1 = 0.f, a2 = 0.f, a3 = 0.f;
        #pragma unroll
        for (int j = 0; j < 2; j++) {
            const int idx = lane + 32 * j;
            float4 q = qk4[idx];
            float4 x0 = __ldcs(&k0[idx]);
            float4 x1 = __ldcs(&k1[idx]);
            float4 x2 = __ldcs(&k2[idx]);
            float4 x3 = __ldcs(&k3[idx]);
            a0 += x0.x * q.x + x0.y * q.y + x0.z * q.z + x0.w * q.w;
            a1 += x1.x * q.x + x1.y * q.y + x1.z * q.z + x1.w * q.w;
            a2 += x2.x * q.x + x2.y * q.y + x2.z * q.z + x2.w * q.w;
            a3 += x3.x * q.x + x3.y * q.y + x3.z * q.z + x3.w * q.w;
        }
        #pragma unroll
        for (int off = 16; off; off >>= 1) {
            a0 += __shfl_xor_sync(0xffffffffu, a0, off);
            a1 += __shfl_xor_sync(0xffffffffu, a1, off);
            a2 += __shfl_xor_sync(0xffffffffu, a2, off);
            a3 += __shfl_xor_sync(0xffffffffu, a3, off);
        }
        if (lane == 0) {
            p_sh[r0]     = (a0 + bd) * scale;
            p_sh[r0 + 1] = (a1 + bd) * scale;
            p_sh[r0 + 2] = (a2 + bd) * scale;
            p_sh[r0 + 3] = (a3 + bd) * scale;
        }
    }
    __syncthreads();

    // ---- local softmax partials (threads 0..127)
    float sc = 0.f;
    if (t < CHUNK) {
        sc = p_sh[t];
        float v = sc;
        #pragma unroll
        for (int off = 16; off; off >>= 1)
            v = fmaxf(v, __shfl_xor_sync(0xffffffffu, v, off));
        if (lane == 0) redm[warp] = v;
    }
    __syncthreads();
    const float m = fmaxf(fmaxf(redm[0], redm[1]), fmaxf(redm[2], redm[3]));
    if (t < CHUNK) {
        const float p = __expf(sc - m);
        p_sh[t] = p;                    // own index; visible after next sync
        float sv = p;
        #pragma unroll
        for (int off = 16; off; off >>= 1)
            sv += __shfl_xor_sync(0xffffffffu, sv, off);
        if (lane == 0) redl[warp] = sv;
    }
    __syncthreads();   // weights + redl visible

    // ---- phase 2: float4 column walk, unroll 8
    const int cq = t & 63;
    const int rg = t >> 6;
    const float4* vb = (const float4*)(value + ((size_t)b * S + s0) * C) + cq;
    float4 acc = make_float4(0.f, 0.f, 0.f, 0.f);
    #pragma unroll 8
    for (int s = rg; s < CHUNK; s += 4) {
        const float4 x = __ldcs(&vb[(size_t)s * (C / 4)]);
        const float ws = p_sh[s];
        acc.x += ws * x.x; acc.y += ws * x.y;
        acc.z += ws * x.z; acc.w += ws * x.w;
    }
    red4[rg][cq] = acc;
    __syncthreads();

    const int pidx = b * NCHUNK + blockIdx.x;
    if (t < 64) {
        float4 a0 = red4[0][t], a1 = red4[1][t], a2 = red4[2][t], a3 = red4[3][t];
        float4 r;
        r.x = (a0.x + a1.x) + (a2.x + a3.x);
        r.y = (a0.y + a1.y) + (a2.y + a3.y);
        r.z = (a0.z + a1.z) + (a2.z + a3.z);
        r.w = (a0.w + a1.w) + (a2.w + a3.w);
        ((float4*)(g_cv + (size_t)pidx * C))[t] = r;
    }
    if (t == 0) {
        g_m[pidx] = m;
        g_l[pidx] = redl[0] + redl[1] + redl[2] + redl[3];
    }

    // ---- arrival count (threadfence-reduction pattern)
    __threadfence();
    __syncthreads();
    if (t == 0) ord_sh = atomicAdd(&g_cnt[b], 1);
    __syncthreads();
    const int ord = ord_sh;
    if (ord < NCHUNK - 8) return;

    // === tail projection: this block owns channel slice y ===
    const int y = ord - (NCHUNK - 8);
    if (t == 0) {
        while (atomicAdd(&g_cnt[b], 0) < NCHUNK) __nanosleep(64);
    }
    __syncthreads();
    __threadfence();   // acquire: all 64 chunks' partials now visible

    // gm / gl (threads 0..63 hold the 64 chunk partials)
    float pm = -INFINITY, pl = 0.f;
    if (t < NCHUNK) {
        pm = g_m[b * NCHUNK + t];
        pl = g_l[b * NCHUNK + t];
    }
    float v2 = pm;
    #pragma unroll
    for (int off = 16; off; off >>= 1)
        v2 = fmaxf(v2, __shfl_xor_sync(0xffffffffu, v2, off));
    if (lane == 0 && warp < 2) redm[warp] = v2;
    __syncthreads();
    const float gm = fmaxf(redm[0], redm[1]);
    float w2 = pl * __expf(pm - gm);
    #pragma unroll
    for (int off = 16; off; off >>= 1)
        w2 += __shfl_xor_sync(0xffffffffu, w2, off);
    if (lane == 0 && warp < 2) redl[warp] = w2;
    __syncthreads();
    const float gli = 1.f / (redl[0] + redl[1]);

    // phase A: warp w sums chunks 8w..8w+7 with weight exp(m_i-gm)
    const size_t cvbase = ((size_t)(b * NCHUNK + warp * 8)) * C + y * 32 + lane;
    float a = 0.f;
    #pragma unroll
    for (int i = 0; i < 8; i++) {
        const float wi = __expf(g_m[b * NCHUNK + warp * 8 + i] - gm);
        a += wi * g_cv[cvbase + (size_t)i * C];
    }
    shA[warp][lane] = a;
    __syncthreads();

    if (t < 32) {
        float s = shA[0][t];
        #pragma unroll
        for (int ww = 1; ww < 8; ww++) s += shA[ww][t];
        cx_sh[t] = s * gli;
    }
    __syncthreads();

    // phase B: 32-iteration coalesced Wv walk
    float o = 0.f;
    const float* wv = Wv + (size_t)(y * 32) * OUT + t;
    #pragma unroll 8
    for (int j = 0; j < 32; j++)
        o += cx_sh[j] * wv[(size_t)j * OUT];
    g_po[(size_t)(b * 8 + y) * OUT + t] = o;

    // reset counters for the next graph replay (last projector per batch)
    __threadfence();
    if (t == 0) {
        const int d = atomicAdd(&g_done[b], 1);
        if (d == 7) { g_cnt[b] = 0; g_done[b] = 0; __threadfence(); }
    }
}

// ---------------- kernel 3: assemble ctx + broadcast over S ----------
__global__ void __launch_bounds__(256, 8)
bcast_kernel(const float* __restrict__ bv,
             float* __restrict__ out) {
    const int b = blockIdx.y;
    const int t = threadIdx.x;
    __shared__ float4 ctx4[OUT / 4];  // 64
    if (t < OUT / 4) {
        float4 acc = ((const float4*)bv)[t];
        const float4* po4 = (const float4*)(g_po + (size_t)b * 8 * OUT);
        #pragma unroll
        for (int y = 0; y < 8; y++) {
            const float4 p = po4[y * (OUT / 4) + t];
            acc.x += p.x; acc.y += p.y; acc.z += p.z; acc.w += p.w;
        }
        ctx4[t] = acc;
    }
    __syncthreads();

    const int row = t >> 6;   // 0..3
    const int col = t & 63;   // 0..63
    const float4 val = ctx4[col];
    float4* o4 = (float4*)out;
    const size_t base = ((size_t)b * S + (size_t)blockIdx.x * 64) * (C / 4);
    #pragma unroll
    for (int i = 0; i < 16; i++)
        __stcs(&o4[base + (size_t)(i * 4 + row) * (OUT / 4) + col], val);
}

// ---------------- launch ------------------
extern "C" void kernel_launch(void* const* d_in, const int* in_sizes, int n_in,
                              void* d_out, int out_size) {
    const float* query = (const float*)d_in[0];
    const float* key   = (const float*)d_in[1];
    const float* value = (const float*)d_in[2];
    const float* Wq    = (const float*)d_in[3];
    const float* bq    = (const float*)d_in[4];
    const float* Wk    = (const float*)d_in[5];
    const float* bk    = (const float*)d_in[6];
    const float* Wv    = (const float*)d_in[7];
    const float* bv    = (const float*)d_in[8];
    float* out = (float*)d_out;

    prep_kernel<<<dim3(B, 8), 256>>>(query, Wq, bq, Wk, bk);
    partial_kernel<<<dim3(NCHUNK, B), 256>>>(key, value, Wv);
    bcast_kernel<<<dim3(S / 64, B), 256>>>(bv, out);
}